// round 1
// baseline (speedup 1.0000x reference)
#include <cuda_runtime.h>

// Problem constants (fixed by the reference)
#define B_  8192
#define D_  1024
#define O_  1024
#define E_  8
#define K_  (E_ * D_)   // 8192 — fused GEMM K dimension

// GEMM tiling
#define BM 128
#define BN 128
#define BK 8
#define TM 8
#define TN 8
#define NTHREADS 256
#define NK (K_ / BK)    // 1024 k-stages

// Scratch: softmax gates [B, E] (static device global — no allocation)
__device__ float g_gates[B_ * E_];

// ---------------------------------------------------------------------------
// Kernel 1: gating — one warp per row. logits = x[b]·Wg + bg, softmax over E=8.
// ---------------------------------------------------------------------------
__global__ void gates_kernel(const float* __restrict__ x,
                             const float* __restrict__ Wg,
                             const float* __restrict__ bg) {
    int warp = (blockIdx.x * blockDim.x + threadIdx.x) >> 5;
    int lane = threadIdx.x & 31;
    if (warp >= B_) return;

    const float* xr = x + (size_t)warp * D_;
    float acc[E_];
#pragma unroll
    for (int e = 0; e < E_; e++) acc[e] = 0.f;

    for (int d = lane; d < D_; d += 32) {
        float xv = xr[d];
        const float4* w4 = reinterpret_cast<const float4*>(Wg + d * E_);
        float4 w0 = w4[0], w1 = w4[1];
        acc[0] += xv * w0.x; acc[1] += xv * w0.y;
        acc[2] += xv * w0.z; acc[3] += xv * w0.w;
        acc[4] += xv * w1.x; acc[5] += xv * w1.y;
        acc[6] += xv * w1.z; acc[7] += xv * w1.w;
    }
#pragma unroll
    for (int e = 0; e < E_; e++) {
#pragma unroll
        for (int off = 16; off; off >>= 1)
            acc[e] += __shfl_xor_sync(0xffffffffu, acc[e], off);
    }
    if (lane == 0) {
        float m = -1e30f;
#pragma unroll
        for (int e = 0; e < E_; e++) { acc[e] += bg[e]; m = fmaxf(m, acc[e]); }
        float s = 0.f;
#pragma unroll
        for (int e = 0; e < E_; e++) { acc[e] = expf(acc[e] - m); s += acc[e]; }
        float inv = 1.f / s;
#pragma unroll
        for (int e = 0; e < E_; e++) g_gates[warp * E_ + e] = acc[e] * inv;
    }
}

// ---------------------------------------------------------------------------
// Kernel 2: fused MoE GEMM.
//   out[b, o] = sum_k A'[b,k] * W'[k,o] + sum_e g[b,e]*be[e,o]
//   A'[b, k] = g[b, k>>10] * x[b, k&1023]     (gate factor constant per BK stage)
//   W'[k, o] = We viewed as row-major [8192, 1024]
// 128x128x8 tiles, 256 threads, 8x8 register microtiles, reg-prefetch pipeline.
// ---------------------------------------------------------------------------
__global__ __launch_bounds__(NTHREADS, 2)
void moe_gemm_kernel(const float* __restrict__ x,
                     const float* __restrict__ We,
                     const float* __restrict__ be,
                     float* __restrict__ out) {
    __shared__ float As[BK][BM];     // A tile, transposed (k-major)
    __shared__ float Bs[BK][BN];
    __shared__ float Gs[BM][E_];     // gates for this block's 128 rows
    __shared__ float BEs[E_][BN];    // bias tile for this block's 128 cols

    const int tid = threadIdx.x;
    const int m0  = blockIdx.y * BM;
    const int n0  = blockIdx.x * BN;

    // One-time loads: gates (128x8 = 1024 f) and bias tile (8x128 = 1024 f)
    {
        float4 gv = reinterpret_cast<const float4*>(g_gates + (size_t)m0 * E_)[tid];
        reinterpret_cast<float4*>(&Gs[0][0])[tid] = gv;
        int r = tid >> 5;             // expert 0..7
        int c = (tid & 31) * 4;       // col 0..124
        float4 b4 = *reinterpret_cast<const float4*>(be + r * O_ + n0 + c);
        *reinterpret_cast<float4*>(&BEs[r][c]) = b4;
    }
    __syncthreads();

    // Microtile mapping: 16x16 thread grid, each thread 8 rows x 8 cols
    const int tx = tid & 15;
    const int ty = tid >> 4;
    const int tm = ty * TM;
    const int tn = tx * TN;

    float acc[TM][TN];
#pragma unroll
    for (int i = 0; i < TM; i++)
#pragma unroll
        for (int j = 0; j < TN; j++) acc[i][j] = 0.f;

    // Accumulator init = gate-weighted bias
#pragma unroll
    for (int e = 0; e < E_; e++) {
#pragma unroll
        for (int i = 0; i < TM; i++) {
            float gv = Gs[tm + i][e];
#pragma unroll
            for (int j = 0; j < TN; j++) acc[i][j] += gv * BEs[e][tn + j];
        }
    }

    // Global-load index mapping
    const int am = tid >> 1;              // A: row within tile 0..127
    const int ak = (tid & 1) * 4;         // A: k offset 0 or 4
    const int bkk = tid >> 5;             // B: k row 0..7
    const int bo  = (tid & 31) * 4;       // B: col offset 0..124

    const float* xrow = x + (size_t)(m0 + am) * D_;

    // Stage 0: load + store to smem
    float4 aReg, bReg;
    {
        const int k0 = 0;
        float g = Gs[am][k0 >> 10];
        aReg = *reinterpret_cast<const float4*>(xrow + (k0 & (D_ - 1)) + ak);
        aReg.x *= g; aReg.y *= g; aReg.z *= g; aReg.w *= g;
        bReg = *reinterpret_cast<const float4*>(We + (size_t)(k0 + bkk) * O_ + n0 + bo);
    }
    As[ak + 0][am] = aReg.x; As[ak + 1][am] = aReg.y;
    As[ak + 2][am] = aReg.z; As[ak + 3][am] = aReg.w;
    *reinterpret_cast<float4*>(&Bs[bkk][bo]) = bReg;
    __syncthreads();

    for (int kt = 0; kt < NK; kt++) {
        // Prefetch next stage into registers while computing current
        if (kt + 1 < NK) {
            const int k0 = (kt + 1) * BK;
            float g = Gs[am][k0 >> 10];               // expert constant per stage
            aReg = *reinterpret_cast<const float4*>(xrow + (k0 & (D_ - 1)) + ak);
            aReg.x *= g; aReg.y *= g; aReg.z *= g; aReg.w *= g;
            bReg = *reinterpret_cast<const float4*>(We + (size_t)(k0 + bkk) * O_ + n0 + bo);
        }

        // Compute 8 k-steps from smem
#pragma unroll
        for (int k = 0; k < BK; k++) {
            float a[TM], b[TN];
#pragma unroll
            for (int i = 0; i < TM; i += 4)
                *reinterpret_cast<float4*>(&a[i]) =
                    *reinterpret_cast<const float4*>(&As[k][tm + i]);
#pragma unroll
            for (int j = 0; j < TN; j += 4)
                *reinterpret_cast<float4*>(&b[j]) =
                    *reinterpret_cast<const float4*>(&Bs[k][tn + j]);
#pragma unroll
            for (int i = 0; i < TM; i++)
#pragma unroll
                for (int j = 0; j < TN; j++)
                    acc[i][j] += a[i] * b[j];
        }

        __syncthreads();
        if (kt + 1 < NK) {
            As[ak + 0][am] = aReg.x; As[ak + 1][am] = aReg.y;
            As[ak + 2][am] = aReg.z; As[ak + 3][am] = aReg.w;
            *reinterpret_cast<float4*>(&Bs[bkk][bo]) = bReg;
        }
        __syncthreads();
    }

    // Epilogue: write 8x8 microtile with float4 stores
#pragma unroll
    for (int i = 0; i < TM; i++) {
        float* orow = out + (size_t)(m0 + tm + i) * O_ + n0 + tn;
#pragma unroll
        for (int j = 0; j < TN; j += 4) {
            float4 v = make_float4(acc[i][j], acc[i][j + 1], acc[i][j + 2], acc[i][j + 3]);
            *reinterpret_cast<float4*>(orow + j) = v;
        }
    }
}

// ---------------------------------------------------------------------------
extern "C" void kernel_launch(void* const* d_in, const int* in_sizes, int n_in,
                              void* d_out, int out_size) {
    const float* x  = (const float*)d_in[0];   // [8192, 1024]
    const float* Wg = (const float*)d_in[1];   // [1024, 8]
    const float* bg = (const float*)d_in[2];   // [8]
    const float* We = (const float*)d_in[3];   // [8, 1024, 1024] == W' [8192, 1024]
    const float* be = (const float*)d_in[4];   // [8, 1024]
    float* out = (float*)d_out;                // [8192, 1024]

    // 8 warps per block, one warp per row -> 1024 blocks
    gates_kernel<<<B_ / 8, 256>>>(x, Wg, bg);

    dim3 grid(O_ / BN, B_ / BM);               // (8, 64) = 512 blocks
    moe_gemm_kernel<<<grid, NTHREADS>>>(x, We, be, out);
}

// round 8
// speedup vs baseline: 3.0897x; 3.0897x over previous
#include <cuda_runtime.h>
#include <cuda_bf16.h>
#include <cstdint>

// ---------------------------------------------------------------------------
// Problem constants
// ---------------------------------------------------------------------------
#define B_  8192
#define D_  1024
#define O_  1024
#define E_  8

// GEMM tiling
#define BM 128
#define BN 128
#define BKE 64                      // bf16 k-elements per stage (128 B rows)
#define STAGES 3
#define NST (E_ * D_ / BKE)         // 128 stages (16 per expert)
#define TILEB 16384                 // 128 x 64 bf16 = 16 KB
#define STAGEB (4 * TILEB)          // Ah, Al, Bh, Bl = 64 KB

// SMEM layout
#define SM_GS 0                     // gates: 128 x 8 f32 = 4 KB
#define SM_BE 4096                  // bias tile: 8 x 128 f32 = 4 KB
#define SM_ST 8192
#define SMEM_TOTAL (SM_ST + STAGES * STAGEB)   // 204800 B

// ---------------------------------------------------------------------------
// Scratch (device globals — no allocation)
// ---------------------------------------------------------------------------
__device__ float g_gates[B_ * E_];
__device__ __align__(16) __nv_bfloat16 g_xh[B_ * D_];
__device__ __align__(16) __nv_bfloat16 g_xl[B_ * D_];
__device__ __align__(16) __nv_bfloat16 g_wth[E_ * O_ * D_];   // [e][n][k] K-major
__device__ __align__(16) __nv_bfloat16 g_wtl[E_ * O_ * D_];

// ---------------------------------------------------------------------------
// Helpers
// ---------------------------------------------------------------------------
__device__ __forceinline__ uint32_t smem_u32(const void* p) {
    uint32_t a;
    asm("{ .reg .u64 t; cvta.to.shared.u64 t, %1; cvt.u32.u64 %0, t; }" : "=r"(a) : "l"(p));
    return a;
}
#define SWZ(x) ((x) ^ (((x) >> 3) & 0x70))

__device__ __forceinline__ void cpa16(uint32_t dst, const void* src) {
    asm volatile("cp.async.cg.shared.global [%0], [%1], 16;" :: "r"(dst), "l"(src) : "memory");
}

#define LDSM4(r, addr) \
    asm volatile("ldmatrix.sync.aligned.m8n8.x4.shared.b16 {%0,%1,%2,%3}, [%4];" \
        : "=r"((r)[0]), "=r"((r)[1]), "=r"((r)[2]), "=r"((r)[3]) : "r"(addr))

#define MMA16816(c, a, b) \
    asm volatile("mma.sync.aligned.m16n8k16.row.col.f32.bf16.bf16.f32 " \
        "{%0,%1,%2,%3}, {%4,%5,%6,%7}, {%8,%9}, {%0,%1,%2,%3};" \
        : "+f"((c)[0]), "+f"((c)[1]), "+f"((c)[2]), "+f"((c)[3]) \
        : "r"((a)[0]), "r"((a)[1]), "r"((a)[2]), "r"((a)[3]), \
          "r"((b)[0]), "r"((b)[1]))

// ---------------------------------------------------------------------------
// Kernel 1: gating (validated round 1)
// ---------------------------------------------------------------------------
__global__ void gates_kernel(const float* __restrict__ x,
                             const float* __restrict__ Wg,
                             const float* __restrict__ bg) {
    int warp = (blockIdx.x * blockDim.x + threadIdx.x) >> 5;
    int lane = threadIdx.x & 31;
    if (warp >= B_) return;
    const float* xr = x + (size_t)warp * D_;
    float acc[E_];
#pragma unroll
    for (int e = 0; e < E_; e++) acc[e] = 0.f;
    for (int d = lane; d < D_; d += 32) {
        float xv = xr[d];
        const float4* w4 = reinterpret_cast<const float4*>(Wg + d * E_);
        float4 w0 = w4[0], w1 = w4[1];
        acc[0] += xv * w0.x; acc[1] += xv * w0.y;
        acc[2] += xv * w0.z; acc[3] += xv * w0.w;
        acc[4] += xv * w1.x; acc[5] += xv * w1.y;
        acc[6] += xv * w1.z; acc[7] += xv * w1.w;
    }
#pragma unroll
    for (int e = 0; e < E_; e++)
#pragma unroll
        for (int off = 16; off; off >>= 1)
            acc[e] += __shfl_xor_sync(0xffffffffu, acc[e], off);
    if (lane == 0) {
        float m = -1e30f;
#pragma unroll
        for (int e = 0; e < E_; e++) { acc[e] += bg[e]; m = fmaxf(m, acc[e]); }
        float s = 0.f;
#pragma unroll
        for (int e = 0; e < E_; e++) { acc[e] = expf(acc[e] - m); s += acc[e]; }
        float inv = 1.f / s;
#pragma unroll
        for (int e = 0; e < E_; e++) g_gates[warp * E_ + e] = acc[e] * inv;
    }
}

// ---------------------------------------------------------------------------
// Kernel 2: split x -> bf16 hi/lo
// ---------------------------------------------------------------------------
__global__ void split_x_kernel(const float* __restrict__ x) {
    int i = blockIdx.x * blockDim.x + threadIdx.x;   // over float4s
    if (i >= (B_ * D_) / 4) return;
    float4 v = reinterpret_cast<const float4*>(x)[i];
    float vv[4] = {v.x, v.y, v.z, v.w};
    __nv_bfloat16 h[4], l[4];
#pragma unroll
    for (int c = 0; c < 4; c++) {
        h[c] = __float2bfloat16(vv[c]);
        l[c] = __float2bfloat16(vv[c] - __bfloat162float(h[c]));
    }
    *reinterpret_cast<uint64_t*>(&g_xh[(size_t)i * 4]) = *reinterpret_cast<uint64_t*>(h);
    *reinterpret_cast<uint64_t*>(&g_xl[(size_t)i * 4]) = *reinterpret_cast<uint64_t*>(l);
}

// ---------------------------------------------------------------------------
// Kernel 3: transpose + split We[e][k][n] -> WeT_{h,l}[e][n][k]
// ---------------------------------------------------------------------------
__global__ void split_weT_kernel(const float* __restrict__ We) {
    __shared__ float t[32][33];
    int e = blockIdx.z;
    int k0 = blockIdx.y * 32, n0 = blockIdx.x * 32;
    int tx = threadIdx.x, ty = threadIdx.y;
    const float* base = We + ((size_t)e << 20);
#pragma unroll
    for (int j = 0; j < 4; j++)
        t[ty + j * 8][tx] = base[(size_t)(k0 + ty + j * 8) * O_ + n0 + tx];
    __syncthreads();
    size_t ob = ((size_t)e << 20);
#pragma unroll
    for (int j = 0; j < 4; j++) {
        float v = t[tx][ty + j * 8];
        __nv_bfloat16 h = __float2bfloat16(v);
        __nv_bfloat16 l = __float2bfloat16(v - __bfloat162float(h));
        size_t idx = ob + (size_t)(n0 + ty + j * 8) * D_ + k0 + tx;
        g_wth[idx] = h;
        g_wtl[idx] = l;
    }
}

// ---------------------------------------------------------------------------
// Kernel 4: MoE GEMM on tensor cores via mma.sync (bf16 3-product split)
// ---------------------------------------------------------------------------
__global__ __launch_bounds__(256, 1)
void moe_mma_kernel(const float* __restrict__ be, float* __restrict__ out) {
    extern __shared__ char smem[];
    const uint32_t sb = smem_u32(smem);
    const int tid = threadIdx.x;
    const int lane = tid & 31;
    const int wid = tid >> 5;
    const int warp_m = wid >> 2;        // 0..1  (64-row slabs)
    const int warp_n = wid & 3;         // 0..3  (32-col slabs)
    const int m0 = blockIdx.y * BM;
    const int n0 = blockIdx.x * BN;

    float* gs  = reinterpret_cast<float*>(smem + SM_GS);   // [128][8]
    float* bes = reinterpret_cast<float*>(smem + SM_BE);   // [8][128]
    for (int i = tid; i < BM * E_; i += 256)
        gs[i] = g_gates[(size_t)(m0 + (i >> 3)) * E_ + (i & 7)];
    for (int i = tid; i < E_ * BN; i += 256)
        bes[i] = be[(i >> 7) * O_ + n0 + (i & 127)];

    float acc_t[4][4][4], acc_e[4][4][4];
#pragma unroll
    for (int a = 0; a < 4; a++)
#pragma unroll
        for (int b = 0; b < 4; b++)
#pragma unroll
            for (int c = 0; c < 4; c++) { acc_t[a][b][c] = 0.f; acc_e[a][b][c] = 0.f; }

    // stage loader: 16 x 16B cp.async per thread (Ah, Al, Bh, Bl tiles)
    auto issue = [&](int s) {
        const int buf = s % STAGES;
        const int e = s >> 4, kc = s & 15, koff = kc * BKE;
        const uint32_t sbase = sb + SM_ST + buf * STAGEB;
#pragma unroll
        for (int i = 0; i < 16; i++) {
            int c = tid + i * 256;
            int tile = c >> 10;          // 0:Ah 1:Al 2:Bh 3:Bl
            int rem = c & 1023;
            int r = rem >> 3;            // row (m or n), 0..127
            int k16 = rem & 7;           // 16B chunk in 128B row
            uint32_t dst = sbase + tile * TILEB + SWZ(r * 128 + k16 * 16);
            const __nv_bfloat16* src;
            if (tile < 2)
                src = ((tile == 0) ? g_xh : g_xl)
                    + (size_t)(m0 + r) * D_ + koff + k16 * 8;
            else
                src = ((tile == 2) ? g_wth : g_wtl)
                    + ((size_t)e * O_ + n0 + r) * D_ + koff + k16 * 8;
            cpa16(dst, src);
        }
        asm volatile("cp.async.commit_group;" ::: "memory");
    };

    issue(0);
    issue(1);

    // ldmatrix lane address components
    const int a_row = lane & 15;              // row within 16-row frag
    const int a_kb  = lane >> 4;              // k-halves (0/1 -> +8 elems)
    const int b_row = (lane & 7) + ((lane >> 4) << 3);   // n within 16
    const int b_kb  = (lane >> 3) & 1;

    for (int s = 0; s < NST; s++) {
        asm volatile("cp.async.wait_group 1;" ::: "memory");
        __syncthreads();
        if (s + 2 < NST) issue(s + 2);

        const uint32_t sbase = sb + SM_ST + (s % STAGES) * STAGEB;
        const uint32_t ah_b = sbase;
        const uint32_t al_b = sbase + TILEB;
        const uint32_t bh_b = sbase + 2 * TILEB;
        const uint32_t bl_b = sbase + 3 * TILEB;

#pragma unroll
        for (int kk = 0; kk < 4; kk++) {      // 4 k-steps of 16
            uint32_t ah[4][4], al[4][4], bh[4][2], bl[4][2];
#pragma unroll
            for (int mf = 0; mf < 4; mf++) {
                int row = warp_m * 64 + mf * 16 + a_row;
                uint32_t off = SWZ(row * 128 + kk * 32 + a_kb * 16);
                LDSM4(ah[mf], ah_b + off);
                LDSM4(al[mf], al_b + off);
            }
#pragma unroll
            for (int nf2 = 0; nf2 < 2; nf2++) {
                int row = warp_n * 32 + nf2 * 16 + b_row;
                uint32_t off = SWZ(row * 128 + kk * 32 + b_kb * 16);
                uint32_t t[4];
                LDSM4(t, bh_b + off);
                bh[nf2 * 2][0] = t[0]; bh[nf2 * 2][1] = t[1];
                bh[nf2 * 2 + 1][0] = t[2]; bh[nf2 * 2 + 1][1] = t[3];
                LDSM4(t, bl_b + off);
                bl[nf2 * 2][0] = t[0]; bl[nf2 * 2][1] = t[1];
                bl[nf2 * 2 + 1][0] = t[2]; bl[nf2 * 2 + 1][1] = t[3];
            }
#pragma unroll
            for (int mf = 0; mf < 4; mf++)
#pragma unroll
                for (int nf = 0; nf < 4; nf++) {
                    MMA16816(acc_e[mf][nf], ah[mf], bh[nf]);
                    MMA16816(acc_e[mf][nf], ah[mf], bl[nf]);
                    MMA16816(acc_e[mf][nf], al[mf], bh[nf]);
                }
        }

        if ((s & 15) == 15) {                 // expert boundary
            const int e = s >> 4;
#pragma unroll
            for (int mf = 0; mf < 4; mf++) {
                int r0 = warp_m * 64 + mf * 16 + (lane >> 2);
                float ga = gs[r0 * E_ + e];
                float gb = gs[(r0 + 8) * E_ + e];
#pragma unroll
                for (int nf = 0; nf < 4; nf++) {
                    int n = warp_n * 32 + nf * 8 + (lane & 3) * 2;
                    float be0 = bes[e * BN + n], be1 = bes[e * BN + n + 1];
                    acc_t[mf][nf][0] += ga * (acc_e[mf][nf][0] + be0);
                    acc_t[mf][nf][1] += ga * (acc_e[mf][nf][1] + be1);
                    acc_t[mf][nf][2] += gb * (acc_e[mf][nf][2] + be0);
                    acc_t[mf][nf][3] += gb * (acc_e[mf][nf][3] + be1);
                    acc_e[mf][nf][0] = 0.f; acc_e[mf][nf][1] = 0.f;
                    acc_e[mf][nf][2] = 0.f; acc_e[mf][nf][3] = 0.f;
                }
            }
        }
    }

    // store 64x32 warp tile
#pragma unroll
    for (int mf = 0; mf < 4; mf++) {
        size_t r0 = (size_t)(m0 + warp_m * 64 + mf * 16 + (lane >> 2));
#pragma unroll
        for (int nf = 0; nf < 4; nf++) {
            int n = n0 + warp_n * 32 + nf * 8 + (lane & 3) * 2;
            *reinterpret_cast<float2*>(out + r0 * O_ + n) =
                make_float2(acc_t[mf][nf][0], acc_t[mf][nf][1]);
            *reinterpret_cast<float2*>(out + (r0 + 8) * O_ + n) =
                make_float2(acc_t[mf][nf][2], acc_t[mf][nf][3]);
        }
    }
}

// ---------------------------------------------------------------------------
extern "C" void kernel_launch(void* const* d_in, const int* in_sizes, int n_in,
                              void* d_out, int out_size) {
    const float* x  = (const float*)d_in[0];   // [8192, 1024]
    const float* Wg = (const float*)d_in[1];   // [1024, 8]
    const float* bg = (const float*)d_in[2];   // [8]
    const float* We = (const float*)d_in[3];   // [8, 1024, 1024]
    const float* be = (const float*)d_in[4];   // [8, 1024]
    float* out = (float*)d_out;                // [8192, 1024]

    cudaFuncSetAttribute(moe_mma_kernel,
                         cudaFuncAttributeMaxDynamicSharedMemorySize, SMEM_TOTAL);

    gates_kernel<<<B_ / 8, 256>>>(x, Wg, bg);
    split_x_kernel<<<(B_ * D_ / 4 + 255) / 256, 256>>>(x);
    {
        dim3 g(O_ / 32, D_ / 32, E_);
        dim3 b(32, 8);
        split_weT_kernel<<<g, b>>>(We);
    }
    dim3 grid(O_ / BN, B_ / BM);               // (8, 64) = 512 CTAs
    moe_mma_kernel<<<grid, 256, SMEM_TOTAL>>>(be, out);
}